// round 4
// baseline (speedup 1.0000x reference)
#include <cuda_runtime.h>

// Flow-warp bilinear, smem-tiled, branch-free taps, division-free loader.
// out[b,c,y,x] = bilerp(src[b,c], clamp(y+flow[b,0,y,x]), clamp(x+flow[b,1,y,x]))
// B=8, C=16, H=W=512. Tile 32x32, window 43x43 (margin 4 + 1 for the always-+1 tap),
// 4 channels per CTA, exact global fallback for out-of-window taps.

#define B_ 8
#define C_ 16
#define H_ 512
#define W_ 512
#define HW_ (H_ * W_)
#define CHW_ (C_ * HW_)

#define M_    4
#define TW_   32
#define TH_   32
#define WH    43
#define WW    43
#define PITCH 44
#define CPC   4
#define WIN_CH (WH * PITCH)              // 1892 floats
#define SMEM_BYTES (CPC * WIN_CH * 4)    // 30272 B

__global__ void __launch_bounds__(256) warp_tile_v4_kernel(
    const float* __restrict__ src,
    const float* __restrict__ flow,
    float* __restrict__ out)
{
    extern __shared__ float win[];   // [CPC][WH][PITCH]

    const int tid  = threadIdx.x;
    const int lane = tid & 31;
    const int wrp  = tid >> 5;

    const int tile_x0 = blockIdx.x * TW_;
    const int tile_y0 = blockIdx.y * TH_;
    const int z   = blockIdx.z;
    const int b   = z >> 2;
    const int grp = z & 3;

    const int wx0 = tile_x0 - M_;
    const int wy0 = tile_y0 - M_;
    const int gx  = tile_x0 + lane;

    // ---- per-pixel coordinate precompute (4 pixels/thread: y = tile_y0 + wrp + 8k) ----
    const float* __restrict__ fby = flow + (size_t)b * 2 * HW_;
    const float* __restrict__ fbx = fby + HW_;

    int   s00[4], g00[4], dxg[4], dyg[4];
    float wxv[4], wyv[4];
    bool  inw[4];

#pragma unroll
    for (int k = 0; k < 4; ++k) {
        int y = tile_y0 + wrp + 8 * k;
        float fy = __ldg(fby + y * W_ + gx);
        float fx = __ldg(fbx + y * W_ + gx);
        // reference's normalize->unnormalize cancels exactly
        float py = fminf(fmaxf((float)y  + fy, 0.0f), (float)(H_ - 1));
        float px = fminf(fmaxf((float)gx + fx, 0.0f), (float)(W_ - 1));
        float y0f = floorf(py);
        float x0f = floorf(px);
        wyv[k] = py - y0f;
        wxv[k] = px - x0f;
        int y0 = (int)y0f;               // in [0,511]
        int x0 = (int)x0f;
        int iy0 = y0 - wy0;
        int ix0 = x0 - wx0;
        // need iy0 in [0, WH-2], ix0 in [0, WW-2] so the +1 taps stay in-window
        inw[k] = ((unsigned)iy0 <= (WH - 2)) & ((unsigned)ix0 <= (WW - 2));
        s00[k] = iy0 * PITCH + ix0;
        g00[k] = (y0 << 9) + x0;
        dxg[k] = min(x0 + 1, W_ - 1) - x0;          // 0 or 1 (fallback only)
        dyg[k] = (min(y0 + 1, H_ - 1) - y0) << 9;   // 0 or 512 (fallback only)
    }

    // ---- cooperative window load: 4 channels x 43 rows, warp-per-row ----
    const float* __restrict__ sb = src + (size_t)b * CHW_ + (size_t)grp * CPC * HW_;

    {
        int c = 0, r = wrp;
        for (int it = wrp; it < CPC * WH; it += 8) {
            int sy = min(max(wy0 + r, 0), H_ - 1);
            const float* __restrict__ srow = sb + (size_t)c * HW_ + (sy << 9);
            float* __restrict__ wrow = win + c * WIN_CH + r * PITCH;

            int cx0 = wx0 + lane;
            int sx0 = min(max(cx0, 0), W_ - 1);
            wrow[lane] = __ldg(srow + sx0);
            if (lane < WW - 32) {                 // lanes 0..10
                int sx1 = min(cx0 + 32, W_ - 1);  // >= 28, no lower clamp needed
                wrow[lane + 32] = __ldg(srow + sx1);
            }
            r += 8;
            if (r >= WH) { r -= WH; ++c; }
        }
    }
    __syncthreads();

    // ---- sampling: 4 LDS with immediate offsets per (pixel, channel) ----
    float* __restrict__ ob = out + (size_t)b * CHW_ + (size_t)grp * CPC * HW_
                           + (size_t)(tile_y0 + wrp) * W_ + gx;

#pragma unroll
    for (int c = 0; c < CPC; ++c) {
        const float* __restrict__ wc = win + c * WIN_CH;
        const float* __restrict__ sc = sb + (size_t)c * HW_;
        float* __restrict__ oc = ob + (size_t)c * HW_;
#pragma unroll
        for (int k = 0; k < 4; ++k) {
            float v00, v01, v10, v11;
            if (inw[k]) {
                const float* p = wc + s00[k];
                v00 = p[0];
                v01 = p[1];
                v10 = p[PITCH];
                v11 = p[PITCH + 1];
            } else {   // exact global fallback (|flow| beyond margin; ~never)
                int g = g00[k];
                v00 = __ldg(sc + g);
                v01 = __ldg(sc + g + dxg[k]);
                v10 = __ldg(sc + g + dyg[k]);
                v11 = __ldg(sc + g + dyg[k] + dxg[k]);
            }
            float top = fmaf(wxv[k], v01 - v00, v00);
            float bot = fmaf(wxv[k], v11 - v10, v10);
            oc[(size_t)(8 * k) * W_] = fmaf(wyv[k], bot - top, top);
        }
    }
}

extern "C" void kernel_launch(void* const* d_in, const int* in_sizes, int n_in,
                              void* d_out, int out_size)
{
    const float* src  = (const float*)d_in[0];
    const float* flow = (const float*)d_in[1];
    float* out        = (float*)d_out;

    cudaFuncSetAttribute(warp_tile_v4_kernel,
                         cudaFuncAttributeMaxDynamicSharedMemorySize, SMEM_BYTES);

    dim3 grid(W_ / TW_, H_ / TH_, B_ * (C_ / CPC));   // 16 x 16 x 32
    warp_tile_v4_kernel<<<grid, 256, SMEM_BYTES>>>(src, flow, out);
}

// round 5
// speedup vs baseline: 2.0768x; 2.0768x over previous
#include <cuda_runtime.h>

// Flow-warp bilinear, direct gather, 2 output rows per thread for MLP.
// out[b,c,y,x] = bilerp(src[b,c], clamp(y+flow[b,0,y,x]), clamp(x+flow[b,1,y,x]))
// B=8, C=16, H=W=512.
// Edge trick: if floor(p)==511 after clamp, use x0=510,w=1 -> identical result,
// so the +1 taps never need clamping and never go out of bounds.

#define B_ 8
#define C_ 16
#define H_ 512
#define W_ 512
#define HW_ (H_ * W_)
#define CHW_ (C_ * HW_)

__global__ void __launch_bounds__(256) warp_gather2_kernel(
    const float* __restrict__ src,
    const float* __restrict__ flow,
    float* __restrict__ out)
{
    // grid: x = W/32 * H/2 rows-pairs flattened, z = batch
    // thread handles pixels (b, 2*ry, x) and (b, 2*ry+1, x)
    int idx  = blockIdx.x * blockDim.x + threadIdx.x;   // over W * H/2 = 131072 per batch
    int x    = idx & (W_ - 1);
    int ry   = idx >> 9;            // 0..255
    int b    = blockIdx.z;
    int y    = ry * 2;

    const float* __restrict__ fby = flow + b * 2 * HW_;
    const float* __restrict__ fbx = fby + HW_;

    int   g00[2];                   // base offset of (y0,x0) within a channel plane
    float wxv[2], wyv[2];

#pragma unroll
    for (int k = 0; k < 2; ++k) {
        int yy = y + k;
        int fo = yy * W_ + x;
        float fy = __ldg(fby + fo);
        float fx = __ldg(fbx + fo);
        // normalize->unnormalize in the reference cancels exactly
        float py = fminf(fmaxf((float)yy + fy, 0.0f), (float)(H_ - 1));
        float px = fminf(fmaxf((float)x  + fx, 0.0f), (float)(W_ - 1));
        float y0f = floorf(py);
        float x0f = floorf(px);
        int y0 = min((int)y0f, H_ - 2);   // edge trick: weight becomes exactly 1
        int x0 = min((int)x0f, W_ - 2);
        wyv[k] = py - (float)y0;
        wxv[k] = px - (float)x0;
        g00[k] = (y0 << 9) + x0;
    }

    const float* __restrict__ sb = src + b * CHW_;
    float* __restrict__ ob = out + b * CHW_ + y * W_ + x;

    const int gA = g00[0];
    const int gB = g00[1];

#pragma unroll
    for (int c = 0; c < C_; ++c) {
        const float* __restrict__ sc = sb + c * HW_;
        // pixel A taps (y0,x0) (y0,x0+1) (y0+1,x0) (y0+1,x0+1)
        float a00 = __ldg(sc + gA);
        float a01 = __ldg(sc + gA + 1);
        float a10 = __ldg(sc + gA + W_);
        float a11 = __ldg(sc + gA + W_ + 1);
        // pixel B taps
        float b00 = __ldg(sc + gB);
        float b01 = __ldg(sc + gB + 1);
        float b10 = __ldg(sc + gB + W_);
        float b11 = __ldg(sc + gB + W_ + 1);

        float atop = fmaf(wxv[0], a01 - a00, a00);
        float abot = fmaf(wxv[0], a11 - a10, a10);
        float btop = fmaf(wxv[1], b01 - b00, b00);
        float bbot = fmaf(wxv[1], b11 - b10, b10);

        float* __restrict__ oc = ob + c * HW_;
        oc[0]  = fmaf(wyv[0], abot - atop, atop);
        oc[W_] = fmaf(wyv[1], bbot - btop, btop);
    }
}

extern "C" void kernel_launch(void* const* d_in, const int* in_sizes, int n_in,
                              void* d_out, int out_size)
{
    const float* src  = (const float*)d_in[0];
    const float* flow = (const float*)d_in[1];
    float* out        = (float*)d_out;

    const int per_batch = W_ * (H_ / 2);          // 131072
    dim3 grid(per_batch / 256, 1, B_);
    warp_gather2_kernel<<<grid, 256>>>(src, flow, out);
}